// round 14
// baseline (speedup 1.0000x reference)
#include <cuda_runtime.h>
#include <cuda_fp16.h>
#include <cstdint>

// GATSingleLayer: N=50000, E=1e6, F_IN=256, HEADS=8, F_HEAD=32
#define NN      50000
#define NE      1000000
#define FIN     256
#define HEADS   8
#define FHEAD   32
#define FOUT    256
#define NEG_SLOPE 0.2f
#define NBLK    196              // ceil(NN/256)
#define KC      16               // K chunk
#define NCH     (FIN / KC)       // 16 chunks
#define PAK     20               // A smem pitch over k (floats) - proven conflict-free (R12)
#define PBN     132              // B smem pitch over n (floats) - proven conflict-free (R12)
// dynamic smem (floats): A planes [buf][hi/lo][128][PAK], then B planes [buf][hi/lo][KC][PBN]
#define APL     (128 * PAK)      // 2560 floats per A plane
#define BPL     (KC * PBN)       // 2112 floats per B plane
#define AOF(b, p) (((b) * 2 + (p)) * APL)
#define BOF(b, p) (4 * APL + ((b) * 2 + (p)) * BPL)
#define SMEM_BYTES ((4 * APL + 4 * BPL) * 4)   // 74752

// ---------------- device scratch ----------------
__device__ __align__(16) __half g_hh[(size_t)NN * FOUT]; // 25.6 MB fp16 messages
__device__ __align__(16) float g_asrc[NN * HEADS];
__device__ __align__(16) float g_adst[NN * HEADS];
__device__ __align__(16) float g_wh[FIN * FOUT];         // tf32(W), natural [k][n]
__device__ __align__(16) float g_wl[FIN * FOUT];         // W - tf32(W)
__device__ int g_cnt[NN];
__device__ int g_off[NN + 1];
__device__ int g_cur[NN];
__device__ int g_sorted[NE];
__device__ int g_blk[NBLK];
__device__ int g_blkoff[NBLK];

// ---------------- helpers ----------------
__device__ __forceinline__ uint32_t smem_u32(const void* p) {
    uint32_t a;
    asm("{ .reg .u64 t; cvta.to.shared.u64 t, %1; cvt.u32.u64 %0, t; }" : "=r"(a) : "l"(p));
    return a;
}
__device__ __forceinline__ void cpa16(uint32_t dst, const void* src, int szvalid) {
    asm volatile("cp.async.cg.shared.global [%0], [%1], 16, %2;"
                 :: "r"(dst), "l"(src), "r"(szvalid) : "memory");
}
__device__ __forceinline__ float tf32f(float x) {
    uint32_t u;
    asm("cvt.rna.tf32.f32 %0, %1;" : "=r"(u) : "f"(x));
    return __uint_as_float(u);
}
__device__ __forceinline__ void mma8(float* d, const uint32_t* a, uint32_t b0, uint32_t b1) {
    asm volatile("mma.sync.aligned.m16n8k8.row.col.f32.tf32.tf32.f32 "
                 "{%0,%1,%2,%3}, {%4,%5,%6,%7}, {%8,%9}, {%0,%1,%2,%3};"
                 : "+f"(d[0]), "+f"(d[1]), "+f"(d[2]), "+f"(d[3])
                 : "r"(a[0]), "r"(a[1]), "r"(a[2]), "r"(a[3]), "r"(b0), "r"(b1));
}

// ---------------- K0: zero histogram ----------------
__global__ void k_zero() {
    int i = blockIdx.x * blockDim.x + threadIdx.x;
    if (i < NN) g_cnt[i] = 0;
}

// ---------------- K0b: split W into tf32 hi + fp32 residual (natural layout) -------
__global__ void k_wt(const float* __restrict__ W) {
    int i = blockIdx.x * blockDim.x + threadIdx.x;
    if (i >= FIN * FOUT) return;
    float w = W[i];
    float h = tf32f(w);
    g_wh[i] = h;
    g_wl[i] = w - h;         // raw residual, identical to R12's in-loop split
}

// ---------------- K1: tf32 mma.sync GEMM, pre-split planes, pure LDS+MMA loop ------
__global__ __launch_bounds__(256, 2) void k_gemm(const float* __restrict__ X,
                                                 const float* __restrict__ att_src,
                                                 const float* __restrict__ att_dst) {
    extern __shared__ __align__(16) float smf[];
    __shared__ float s_as[128], s_ad[128];

    const int tid  = threadIdx.x;
    const int wid  = tid >> 5;
    const int lane = tid & 31;
    const int f0   = blockIdx.x * 128;
    const int m0   = blockIdx.y * 128;

    if (tid < 128) {
        s_as[tid] = att_src[f0 + tid];
        s_ad[tid] = att_dst[f0 + tid];
    }

    const int warp_m = wid & 3;           // 0..3 -> 32-row slice
    const int warp_n = wid >> 2;          // 0..1 -> 64-col slice (2 heads)
    const int mb = warp_m * 32;
    const int nb = warp_n * 64;
    const int lr = lane >> 2;             // 0..7
    const int lc = lane & 3;              // 0..3

    // A loader: row = tid>>1, k-half = tid&1 (8 floats per thread per chunk)
    const int rA = tid >> 1;
    const int hA = tid & 1;
    const bool aval = (m0 + rA) < NN;
    // B loader: k row = tid>>5 (and +8), 4 cols at nqB*4
    const int kB = tid >> 5;
    const int nqB = tid & 31;

    float acc[2][8][4];
    #pragma unroll
    for (int i = 0; i < 2; i++)
        #pragma unroll
        for (int j = 0; j < 8; j++)
            #pragma unroll
            for (int q = 0; q < 4; q++) acc[i][j][q] = 0.0f;

    float4 pa0 = make_float4(0.f, 0.f, 0.f, 0.f);
    float4 pa1 = make_float4(0.f, 0.f, 0.f, 0.f);

    auto fetch_a = [&](int kt) {
        if (aval) {
            const float* ap = X + (size_t)(m0 + rA) * FIN + kt * KC + hA * 8;
            pa0 = *(const float4*)ap;
            pa1 = *(const float4*)(ap + 4);
        }
    };
    auto commit_a = [&](int b) {
        float v[8] = {pa0.x, pa0.y, pa0.z, pa0.w, pa1.x, pa1.y, pa1.z, pa1.w};
        float h[8], l[8];
        #pragma unroll
        for (int j = 0; j < 8; j++) { h[j] = tf32f(v[j]); l[j] = v[j] - h[j]; }
        float* d0 = &smf[AOF(b, 0) + rA * PAK + hA * 8];
        float* d1 = &smf[AOF(b, 1) + rA * PAK + hA * 8];
        *(float4*)(d0)     = make_float4(h[0], h[1], h[2], h[3]);
        *(float4*)(d0 + 4) = make_float4(h[4], h[5], h[6], h[7]);
        *(float4*)(d1)     = make_float4(l[0], l[1], l[2], l[3]);
        *(float4*)(d1 + 4) = make_float4(l[4], l[5], l[6], l[7]);
    };
    auto load_b = [&](int kt, int b) {
        const float* s0 = g_wh + (size_t)(kt * KC + kB) * FOUT + f0 + nqB * 4;
        const float* s1 = g_wl + (size_t)(kt * KC + kB) * FOUT + f0 + nqB * 4;
        cpa16(smem_u32(&smf[BOF(b, 0) + kB * PBN + nqB * 4]), s0, 16);
        cpa16(smem_u32(&smf[BOF(b, 0) + (kB + 8) * PBN + nqB * 4]), s0 + 8 * FOUT, 16);
        cpa16(smem_u32(&smf[BOF(b, 1) + kB * PBN + nqB * 4]), s1, 16);
        cpa16(smem_u32(&smf[BOF(b, 1) + (kB + 8) * PBN + nqB * 4]), s1 + 8 * FOUT, 16);
    };

    fetch_a(0);
    load_b(0, 0);
    asm volatile("cp.async.commit_group;" ::: "memory");

    int buf = 0;
    for (int kt = 0; kt < NCH; kt++) {
        commit_a(buf);                        // split + STS this chunk's A (outside k8 loop)
        if (kt + 1 < NCH) {
            load_b(kt + 1, buf ^ 1);
            asm volatile("cp.async.commit_group;" ::: "memory");
            asm volatile("cp.async.wait_group 1;" ::: "memory");
        } else {
            asm volatile("cp.async.wait_group 0;" ::: "memory");
        }
        __syncthreads();

        if (kt + 1 < NCH) fetch_a(kt + 1);    // LDG overlaps MMA below

        #pragma unroll
        for (int k8 = 0; k8 < KC / 8; k8++) {
            const int kb = k8 * 8;
            const int a0o = AOF(buf, 0), a1o = AOF(buf, 1);
            uint32_t ah[2][4], al[2][4];
            #pragma unroll
            for (int wm = 0; wm < 2; wm++) {
                int r = mb + wm * 16 + lr;
                ah[wm][0] = __float_as_uint(smf[a0o + r * PAK + kb + lc]);
                ah[wm][1] = __float_as_uint(smf[a0o + (r + 8) * PAK + kb + lc]);
                ah[wm][2] = __float_as_uint(smf[a0o + r * PAK + kb + lc + 4]);
                ah[wm][3] = __float_as_uint(smf[a0o + (r + 8) * PAK + kb + lc + 4]);
                al[wm][0] = __float_as_uint(smf[a1o + r * PAK + kb + lc]);
                al[wm][1] = __float_as_uint(smf[a1o + (r + 8) * PAK + kb + lc]);
                al[wm][2] = __float_as_uint(smf[a1o + r * PAK + kb + lc + 4]);
                al[wm][3] = __float_as_uint(smf[a1o + (r + 8) * PAK + kb + lc + 4]);
            }
            const int b0o = BOF(buf, 0), b1o = BOF(buf, 1);
            #pragma unroll
            for (int wn = 0; wn < 8; wn++) {
                int bc = nb + wn * 8 + lr;
                uint32_t bh0 = __float_as_uint(smf[b0o + (kb + lc) * PBN + bc]);
                uint32_t bh1 = __float_as_uint(smf[b0o + (kb + lc + 4) * PBN + bc]);
                uint32_t bl0 = __float_as_uint(smf[b1o + (kb + lc) * PBN + bc]);
                uint32_t bl1 = __float_as_uint(smf[b1o + (kb + lc + 4) * PBN + bc]);
                #pragma unroll
                for (int wm = 0; wm < 2; wm++) {
                    mma8(acc[wm][wn], ah[wm], bh0, bh1);
                    mma8(acc[wm][wn], al[wm], bh0, bh1);
                    mma8(acc[wm][wn], ah[wm], bl0, bl1);
                }
            }
        }
        __syncthreads();
        buf ^= 1;
    }

    // ---- epilogue: h store (fp16) + fused a_src/a_dst (unchanged from R12) ----
    #pragma unroll
    for (int wm = 0; wm < 2; wm++) {
        #pragma unroll
        for (int half = 0; half < 2; half++) {
            int m = m0 + mb + wm * 16 + half * 8 + lr;
            bool mval = m < NN;
            if (mval) {
                __half* hp = g_hh + (size_t)m * FOUT + f0 + nb + lc * 2;
                #pragma unroll
                for (int wn = 0; wn < 8; wn++) {
                    __half2 hv = __floats2half2_rn(acc[wm][wn][2 * half],
                                                   acc[wm][wn][2 * half + 1]);
                    *(__half2*)(hp + wn * 8) = hv;
                }
            }
            float psA = 0.f, pdA = 0.f, psB = 0.f, pdB = 0.f;
            #pragma unroll
            for (int wn = 0; wn < 8; wn++) {
                int col = nb + wn * 8 + lc * 2;
                float v0 = acc[wm][wn][2 * half];
                float v1 = acc[wm][wn][2 * half + 1];
                float s = v0 * s_as[col] + v1 * s_as[col + 1];
                float d = v0 * s_ad[col] + v1 * s_ad[col + 1];
                if (wn < 4) { psA += s; pdA += d; }
                else        { psB += s; pdB += d; }
            }
            #pragma unroll
            for (int off = 1; off < 4; off <<= 1) {
                psA += __shfl_xor_sync(0xffffffffu, psA, off);
                pdA += __shfl_xor_sync(0xffffffffu, pdA, off);
                psB += __shfl_xor_sync(0xffffffffu, psB, off);
                pdB += __shfl_xor_sync(0xffffffffu, pdB, off);
            }
            if (lc == 0 && mval) {
                int headA = ((f0 + nb) >> 5);
                g_asrc[m * HEADS + headA]     = psA;
                g_adst[m * HEADS + headA]     = pdA;
                g_asrc[m * HEADS + headA + 1] = psB;
                g_adst[m * HEADS + headA + 1] = pdB;
            }
        }
    }
}

// ---------------- K2: degree histogram ----------------
__global__ __launch_bounds__(256) void k_hist(const int* __restrict__ ei) {
    int e = blockIdx.x * blockDim.x + threadIdx.x;
    if (e < NE) atomicAdd(&g_cnt[ei[NE + e]], 1);
}

// ---------------- K3a/b/c: multi-block scan ----------------
__global__ __launch_bounds__(256) void k_scan1() {
    __shared__ int sp[256];
    int b = blockIdx.x, t = threadIdx.x;
    int idx = b * 256 + t;
    int v = (idx < NN) ? g_cnt[idx] : 0;
    sp[t] = v;
    __syncthreads();
    #pragma unroll
    for (int off = 1; off < 256; off <<= 1) {
        int u = (t >= off) ? sp[t - off] : 0;
        __syncthreads();
        sp[t] += u;
        __syncthreads();
    }
    if (idx < NN) g_off[idx] = sp[t] - v;
    if (t == 255) g_blk[b] = sp[255];
}
__global__ __launch_bounds__(256) void k_scan2() {
    __shared__ int sp[256];
    int t = threadIdx.x;
    int v = (t < NBLK) ? g_blk[t] : 0;
    sp[t] = v;
    __syncthreads();
    #pragma unroll
    for (int off = 1; off < 256; off <<= 1) {
        int u = (t >= off) ? sp[t - off] : 0;
        __syncthreads();
        sp[t] += u;
        __syncthreads();
    }
    if (t < NBLK) g_blkoff[t] = sp[t] - v;
}
__global__ __launch_bounds__(256) void k_scan3() {
    int idx = blockIdx.x * blockDim.x + threadIdx.x;
    if (idx < NN) {
        int o = g_off[idx] + g_blkoff[idx >> 8];
        g_off[idx] = o;
        g_cur[idx] = o;
    }
    if (idx == 0) g_off[NN] = NE;
}

// ---------------- K4: scatter ----------------
__global__ __launch_bounds__(256) void k_scatter(const int* __restrict__ ei) {
    int e = blockIdx.x * blockDim.x + threadIdx.x;
    if (e >= NE) return;
    int src = ei[e];
    int dst = ei[NE + e];
    int p = atomicAdd(&g_cur[dst], 1);
    g_sorted[p] = src;
}

// ---------------- K5: per-node softmax + weighted aggregation (warp per node) ------
__global__ __launch_bounds__(256) void k_node(const float* __restrict__ bias,
                                              float* __restrict__ out) {
    int n = (blockIdx.x * blockDim.x + threadIdx.x) >> 5;
    if (n >= NN) return;
    int lane = threadIdx.x & 31;

    int s0 = g_off[n];
    int s1 = g_off[n + 1];

    float ad = g_adst[n * HEADS + (lane & 7)];

    float den = 0.0f;
    for (int e = s0; e < s1; e++) {
        int s = g_sorted[e];
        float v = g_asrc[s * HEADS + (lane & 7)] + ad;
        v = (v > 0.0f) ? v : NEG_SLOPE * v;
        den += __expf(v);
    }
    float rden = (den > 0.0f) ? (1.0f / den) : 0.0f;

    float acc[8];
    #pragma unroll
    for (int j = 0; j < 8; j++) acc[j] = 0.0f;

    for (int e = s0; e < s1; e++) {
        int s = g_sorted[e];
        float v = g_asrc[s * HEADS + (lane & 7)] + ad;
        v = (v > 0.0f) ? v : NEG_SLOPE * v;
        float al = __expf(v) * rden;
        float a = __shfl_sync(0xffffffffu, al, lane >> 2);   // head for my 8 cols
        uint4 hv = *(const uint4*)(g_hh + (size_t)s * FOUT + lane * 8);
        const __half2* hp = (const __half2*)&hv;
        #pragma unroll
        for (int j = 0; j < 4; j++) {
            float2 f = __half22float2(hp[j]);
            acc[2 * j]     += a * f.x;
            acc[2 * j + 1] += a * f.y;
        }
    }

    const float* bp = bias + lane * 8;
    float* op = out + (size_t)n * FOUT + lane * 8;
    float4 o0 = make_float4(acc[0] + bp[0], acc[1] + bp[1], acc[2] + bp[2], acc[3] + bp[3]);
    float4 o1 = make_float4(acc[4] + bp[4], acc[5] + bp[5], acc[6] + bp[6], acc[7] + bp[7]);
    *(float4*)(op)     = o0;
    *(float4*)(op + 4) = o1;
}

// ---------------- launch ----------------
extern "C" void kernel_launch(void* const* d_in, const int* in_sizes, int n_in,
                              void* d_out, int out_size) {
    const float* x       = (const float*)d_in[0];
    const float* W       = (const float*)d_in[1];
    const float* att_src = (const float*)d_in[2];
    const float* att_dst = (const float*)d_in[3];
    const float* bias    = (const float*)d_in[4];
    const int*   ei      = (const int*)d_in[5];
    float*       out     = (float*)d_out;

    cudaFuncSetAttribute(k_gemm, cudaFuncAttributeMaxDynamicSharedMemorySize, SMEM_BYTES);

    int eb = (NE + 255) / 256;

    k_zero<<<(NN + 255) / 256, 256>>>();                 // 1
    k_wt<<<(FIN * FOUT + 255) / 256, 256>>>(W);          // 2
    k_hist<<<eb, 256>>>(ei);                             // 3

    dim3 ggrid(FOUT / 128, (NN + 127) / 128);            // (2, 391)
    k_gemm<<<ggrid, 256, SMEM_BYTES>>>(x, att_src, att_dst);  // 4 <- profiled slot

    k_scan1<<<NBLK, 256>>>();                            // 5
    k_scan2<<<1, 256>>>();                               // 6
    k_scan3<<<NBLK, 256>>>();                            // 7
    k_scatter<<<eb, 256>>>(ei);                          // 8
    k_node<<<(NN * 32 + 255) / 256, 256>>>(bias, out);   // 9
}

// round 15
// speedup vs baseline: 1.2318x; 1.2318x over previous
#include <cuda_runtime.h>
#include <cuda_fp16.h>
#include <cstdint>

// GATSingleLayer: N=50000, E=1e6, F_IN=256, HEADS=8, F_HEAD=32
#define NN      50000
#define NE      1000000
#define FIN     256
#define HEADS   8
#define FHEAD   32
#define FOUT    256
#define NEG_SLOPE 0.2f
#define NBLK    196              // ceil(NN/256)
#define KC      16               // K chunk
#define NCH     (FIN / KC)       // 16 chunks
#define PAK     20               // A smem pitch over k (floats): conflict-free (proven R12)
#define PBN     132              // B smem pitch over n (floats): conflict-free (proven R12)

// ---------------- device scratch ----------------
__device__ __align__(16) __half g_hh[(size_t)NN * FOUT]; // 25.6 MB fp16 messages
__device__ __align__(16) float g_asrc[NN * HEADS];
__device__ __align__(16) float g_adst[NN * HEADS];
__device__ int g_cnt[NN];
__device__ int g_off[NN + 1];
__device__ int g_cur[NN];
__device__ int g_sorted[NE];
__device__ int g_blk[NBLK];
__device__ int g_blkoff[NBLK];

// ---------------- helpers ----------------
__device__ __forceinline__ uint32_t smem_u32(const void* p) {
    uint32_t a;
    asm("{ .reg .u64 t; cvta.to.shared.u64 t, %1; cvt.u32.u64 %0, t; }" : "=r"(a) : "l"(p));
    return a;
}
__device__ __forceinline__ void cpa16(uint32_t dst, const void* src, int szvalid) {
    asm volatile("cp.async.cg.shared.global [%0], [%1], 16, %2;"
                 :: "r"(dst), "l"(src), "r"(szvalid) : "memory");
}
__device__ __forceinline__ uint32_t tf32r(float x) {
    uint32_t u;
    asm("cvt.rna.tf32.f32 %0, %1;" : "=r"(u) : "f"(x));
    return u;
}
__device__ __forceinline__ void mma8(float* d, const uint32_t* a, uint32_t b0, uint32_t b1) {
    asm volatile("mma.sync.aligned.m16n8k8.row.col.f32.tf32.tf32.f32 "
                 "{%0,%1,%2,%3}, {%4,%5,%6,%7}, {%8,%9}, {%0,%1,%2,%3};"
                 : "+f"(d[0]), "+f"(d[1]), "+f"(d[2]), "+f"(d[3])
                 : "r"(a[0]), "r"(a[1]), "r"(a[2]), "r"(a[3]), "r"(b0), "r"(b1));
}

// ---------------- K0: zero histogram ----------------
__global__ void k_zero() {
    int i = blockIdx.x * blockDim.x + threadIdx.x;
    if (i < NN) g_cnt[i] = 0;
}

// ---------------- K1: tf32 mma.sync GEMM, 128x128 tile, cp.async, 2 CTAs/SM --------
// 2-product split: h = (a_hi + a_lo) * b_hi ; dropped a_hi*b_lo term (~2.8e-4 rel).
__global__ __launch_bounds__(256, 2) void k_gemm(const float* __restrict__ X,
                                                 const float* __restrict__ W,
                                                 const float* __restrict__ att_src,
                                                 const float* __restrict__ att_dst) {
    __shared__ __align__(16) float As[2][128][PAK];   // [buf][m][k]
    __shared__ __align__(16) float Bs[2][KC][PBN];    // [buf][k][n]
    __shared__ float s_as[128], s_ad[128];

    const int tid  = threadIdx.x;
    const int wid  = tid >> 5;
    const int lane = tid & 31;
    const int f0   = blockIdx.x * 128;
    const int m0   = blockIdx.y * 128;

    if (tid < 128) {
        s_as[tid] = att_src[f0 + tid];
        s_ad[tid] = att_dst[f0 + tid];
    }

    const int warp_m = wid & 3;           // 0..3 -> 32-row slice
    const int warp_n = wid >> 2;          // 0..1 -> 64-col slice (2 heads)
    const int mb = warp_m * 32;
    const int nb = warp_n * 64;
    const int lr = lane >> 2;             // 0..7
    const int lc = lane & 3;              // 0..3

    // async loaders: 2 x 16B per thread per operand per chunk
    const int rA = tid >> 2;
    const int qA = tid & 3;
    const int kB = tid >> 5;
    const int nqB = tid & 31;

    float acc[2][8][4];
    #pragma unroll
    for (int i = 0; i < 2; i++)
        #pragma unroll
        for (int j = 0; j < 8; j++)
            #pragma unroll
            for (int q = 0; q < 4; q++) acc[i][j][q] = 0.0f;

    auto load_chunk = [&](int kt, int buf) {
        #pragma unroll
        for (int j = 0; j < 2; j++) {
            int r = rA + 64 * j;
            int valid = (m0 + r) < NN ? 16 : 0;
            cpa16(smem_u32(&As[buf][r][qA * 4]),
                  X + (size_t)(m0 + r) * FIN + kt * KC + qA * 4, valid);
        }
        #pragma unroll
        for (int j = 0; j < 2; j++) {
            int k = kB + 8 * j;
            cpa16(smem_u32(&Bs[buf][k][nqB * 4]),
                  W + (size_t)(kt * KC + k) * FOUT + f0 + nqB * 4, 16);
        }
    };

    load_chunk(0, 0);
    asm volatile("cp.async.commit_group;" ::: "memory");

    int buf = 0;
    for (int kt = 0; kt < NCH; kt++) {
        if (kt + 1 < NCH) {
            load_chunk(kt + 1, buf ^ 1);
            asm volatile("cp.async.commit_group;" ::: "memory");
            asm volatile("cp.async.wait_group 1;" ::: "memory");
        } else {
            asm volatile("cp.async.wait_group 0;" ::: "memory");
        }
        __syncthreads();

        #pragma unroll
        for (int k8 = 0; k8 < KC / 8; k8++) {
            const int kb = k8 * 8;
            uint32_t ahi[2][4], alo[2][4];
            #pragma unroll
            for (int wm = 0; wm < 2; wm++) {
                int r = mb + wm * 16 + lr;
                float a0 = As[buf][r][kb + lc];
                float a1 = As[buf][r + 8][kb + lc];
                float a2 = As[buf][r][kb + lc + 4];
                float a3 = As[buf][r + 8][kb + lc + 4];
                ahi[wm][0] = tf32r(a0); alo[wm][0] = __float_as_uint(a0 - __uint_as_float(ahi[wm][0]));
                ahi[wm][1] = tf32r(a1); alo[wm][1] = __float_as_uint(a1 - __uint_as_float(ahi[wm][1]));
                ahi[wm][2] = tf32r(a2); alo[wm][2] = __float_as_uint(a2 - __uint_as_float(ahi[wm][2]));
                ahi[wm][3] = tf32r(a3); alo[wm][3] = __float_as_uint(a3 - __uint_as_float(ahi[wm][3]));
            }
            #pragma unroll
            for (int wn = 0; wn < 8; wn++) {
                int bc = nb + wn * 8 + lr;
                uint32_t bh0 = tf32r(Bs[buf][kb + lc][bc]);
                uint32_t bh1 = tf32r(Bs[buf][kb + lc + 4][bc]);
                #pragma unroll
                for (int wm = 0; wm < 2; wm++) {
                    mma8(acc[wm][wn], ahi[wm], bh0, bh1);
                    mma8(acc[wm][wn], alo[wm], bh0, bh1);
                }
            }
        }
        __syncthreads();
        buf ^= 1;
    }

    // ---- epilogue: h store (fp16) + fused a_src/a_dst ----
    // acc frag: d0=(lr, 2lc), d1=(lr, 2lc+1), d2=(lr+8, 2lc), d3=(lr+8, 2lc+1)
    #pragma unroll
    for (int wm = 0; wm < 2; wm++) {
        #pragma unroll
        for (int half = 0; half < 2; half++) {
            int m = m0 + mb + wm * 16 + half * 8 + lr;
            bool mval = m < NN;
            if (mval) {
                __half* hp = g_hh + (size_t)m * FOUT + f0 + nb + lc * 2;
                #pragma unroll
                for (int wn = 0; wn < 8; wn++) {
                    __half2 hv = __floats2half2_rn(acc[wm][wn][2 * half],
                                                   acc[wm][wn][2 * half + 1]);
                    *(__half2*)(hp + wn * 8) = hv;
                }
            }
            float psA = 0.f, pdA = 0.f, psB = 0.f, pdB = 0.f;
            #pragma unroll
            for (int wn = 0; wn < 8; wn++) {
                int col = nb + wn * 8 + lc * 2;
                float v0 = acc[wm][wn][2 * half];
                float v1 = acc[wm][wn][2 * half + 1];
                float s = v0 * s_as[col] + v1 * s_as[col + 1];
                float d = v0 * s_ad[col] + v1 * s_ad[col + 1];
                if (wn < 4) { psA += s; pdA += d; }
                else        { psB += s; pdB += d; }
            }
            #pragma unroll
            for (int off = 1; off < 4; off <<= 1) {
                psA += __shfl_xor_sync(0xffffffffu, psA, off);
                pdA += __shfl_xor_sync(0xffffffffu, pdA, off);
                psB += __shfl_xor_sync(0xffffffffu, psB, off);
                pdB += __shfl_xor_sync(0xffffffffu, pdB, off);
            }
            if (lc == 0 && mval) {
                int headA = ((f0 + nb) >> 5);
                g_asrc[m * HEADS + headA]     = psA;
                g_adst[m * HEADS + headA]     = pdA;
                g_asrc[m * HEADS + headA + 1] = psB;
                g_adst[m * HEADS + headA + 1] = pdB;
            }
        }
    }
}

// ---------------- K2: degree histogram ----------------
__global__ __launch_bounds__(256) void k_hist(const int* __restrict__ ei) {
    int e = blockIdx.x * blockDim.x + threadIdx.x;
    if (e < NE) atomicAdd(&g_cnt[ei[NE + e]], 1);
}

// ---------------- K3a/b/c: multi-block scan ----------------
__global__ __launch_bounds__(256) void k_scan1() {
    __shared__ int sp[256];
    int b = blockIdx.x, t = threadIdx.x;
    int idx = b * 256 + t;
    int v = (idx < NN) ? g_cnt[idx] : 0;
    sp[t] = v;
    __syncthreads();
    #pragma unroll
    for (int off = 1; off < 256; off <<= 1) {
        int u = (t >= off) ? sp[t - off] : 0;
        __syncthreads();
        sp[t] += u;
        __syncthreads();
    }
    if (idx < NN) g_off[idx] = sp[t] - v;
    if (t == 255) g_blk[b] = sp[255];
}
__global__ __launch_bounds__(256) void k_scan2() {
    __shared__ int sp[256];
    int t = threadIdx.x;
    int v = (t < NBLK) ? g_blk[t] : 0;
    sp[t] = v;
    __syncthreads();
    #pragma unroll
    for (int off = 1; off < 256; off <<= 1) {
        int u = (t >= off) ? sp[t - off] : 0;
        __syncthreads();
        sp[t] += u;
        __syncthreads();
    }
    if (t < NBLK) g_blkoff[t] = sp[t] - v;
}
__global__ __launch_bounds__(256) void k_scan3() {
    int idx = blockIdx.x * blockDim.x + threadIdx.x;
    if (idx < NN) {
        int o = g_off[idx] + g_blkoff[idx >> 8];
        g_off[idx] = o;
        g_cur[idx] = o;
    }
    if (idx == 0) g_off[NN] = NE;
}

// ---------------- K4: scatter ----------------
__global__ __launch_bounds__(256) void k_scatter(const int* __restrict__ ei) {
    int e = blockIdx.x * blockDim.x + threadIdx.x;
    if (e >= NE) return;
    int src = ei[e];
    int dst = ei[NE + e];
    int p = atomicAdd(&g_cur[dst], 1);
    g_sorted[p] = src;
}

// ---------------- K5: per-node softmax + weighted aggregation (warp per node) ------
__global__ __launch_bounds__(256) void k_node(const float* __restrict__ bias,
                                              float* __restrict__ out) {
    int n = (blockIdx.x * blockDim.x + threadIdx.x) >> 5;
    if (n >= NN) return;
    int lane = threadIdx.x & 31;

    int s0 = g_off[n];
    int s1 = g_off[n + 1];

    float ad = g_adst[n * HEADS + (lane & 7)];

    float den = 0.0f;
    for (int e = s0; e < s1; e++) {
        int s = g_sorted[e];
        float v = g_asrc[s * HEADS + (lane & 7)] + ad;
        v = (v > 0.0f) ? v : NEG_SLOPE * v;
        den += __expf(v);
    }
    float rden = (den > 0.0f) ? (1.0f / den) : 0.0f;

    float acc[8];
    #pragma unroll
    for (int j = 0; j < 8; j++) acc[j] = 0.0f;

    for (int e = s0; e < s1; e++) {
        int s = g_sorted[e];
        float v = g_asrc[s * HEADS + (lane & 7)] + ad;
        v = (v > 0.0f) ? v : NEG_SLOPE * v;
        float al = __expf(v) * rden;
        float a = __shfl_sync(0xffffffffu, al, lane >> 2);   // head for my 8 cols
        uint4 hv = *(const uint4*)(g_hh + (size_t)s * FOUT + lane * 8);
        const __half2* hp = (const __half2*)&hv;
        #pragma unroll
        for (int j = 0; j < 4; j++) {
            float2 f = __half22float2(hp[j]);
            acc[2 * j]     += a * f.x;
            acc[2 * j + 1] += a * f.y;
        }
    }

    const float* bp = bias + lane * 8;
    float* op = out + (size_t)n * FOUT + lane * 8;
    float4 o0 = make_float4(acc[0] + bp[0], acc[1] + bp[1], acc[2] + bp[2], acc[3] + bp[3]);
    float4 o1 = make_float4(acc[4] + bp[4], acc[5] + bp[5], acc[6] + bp[6], acc[7] + bp[7]);
    *(float4*)(op)     = o0;
    *(float4*)(op + 4) = o1;
}

// ---------------- launch ----------------
extern "C" void kernel_launch(void* const* d_in, const int* in_sizes, int n_in,
                              void* d_out, int out_size) {
    const float* x       = (const float*)d_in[0];
    const float* W       = (const float*)d_in[1];
    const float* att_src = (const float*)d_in[2];
    const float* att_dst = (const float*)d_in[3];
    const float* bias    = (const float*)d_in[4];
    const int*   ei      = (const int*)d_in[5];
    float*       out     = (float*)d_out;

    int eb = (NE + 255) / 256;

    k_zero<<<(NN + 255) / 256, 256>>>();          // 1
    k_hist<<<eb, 256>>>(ei);                      // 2
    k_scan1<<<NBLK, 256>>>();                     // 3

    dim3 ggrid(FOUT / 128, (NN + 127) / 128);     // (2, 391)
    k_gemm<<<ggrid, 256>>>(x, W, att_src, att_dst);  // 4  <- profiled slot

    k_scan2<<<1, 256>>>();                        // 5
    k_scan3<<<NBLK, 256>>>();                     // 6
    k_scatter<<<eb, 256>>>(ei);                   // 7
    k_node<<<(NN * 32 + 255) / 256, 256>>>(bias, out);  // 8
}

// round 16
// speedup vs baseline: 1.4440x; 1.1722x over previous
#include <cuda_runtime.h>
#include <cuda_fp16.h>
#include <cstdint>

// GATSingleLayer: N=50000, E=1e6, F_IN=256, HEADS=8, F_HEAD=32
#define NN      50000
#define NE      1000000
#define FIN     256
#define HEADS   8
#define FHEAD   32
#define FOUT    256
#define NEG_SLOPE 0.2f
#define NBLK    196              // ceil(NN/256)
#define KC      16               // K chunk
#define NCH     (FIN / KC)       // 16 chunks
#define PAK     20               // A smem pitch over k (floats): conflict-free (proven)
#define PBN     132              // B smem pitch over n (floats): conflict-free (proven)

// ---------------- device scratch ----------------
__device__ __align__(16) __half g_hh[(size_t)NN * FOUT]; // 25.6 MB fp16 messages
__device__ __align__(16) float g_asrc[NN * HEADS];
__device__ __align__(16) float g_adst[NN * HEADS];
__device__ __align__(16) float g_wh[FIN * FOUT];         // tf32-rounded W (fp32 bits)
__device__ int g_cnt[NN];
__device__ int g_off[NN + 1];
__device__ int g_cur[NN];
__device__ int g_sorted[NE];
__device__ int g_blk[NBLK];
__device__ int g_blkoff[NBLK];

// ---------------- helpers ----------------
__device__ __forceinline__ uint32_t smem_u32(const void* p) {
    uint32_t a;
    asm("{ .reg .u64 t; cvta.to.shared.u64 t, %1; cvt.u32.u64 %0, t; }" : "=r"(a) : "l"(p));
    return a;
}
__device__ __forceinline__ void cpa16(uint32_t dst, const void* src, int szvalid) {
    asm volatile("cp.async.cg.shared.global [%0], [%1], 16, %2;"
                 :: "r"(dst), "l"(src), "r"(szvalid) : "memory");
}
__device__ __forceinline__ uint32_t tf32r(float x) {
    uint32_t u;
    asm("cvt.rna.tf32.f32 %0, %1;" : "=r"(u) : "f"(x));
    return u;
}
__device__ __forceinline__ void mma8(float* d, const uint32_t* a, uint32_t b0, uint32_t b1) {
    asm volatile("mma.sync.aligned.m16n8k8.row.col.f32.tf32.tf32.f32 "
                 "{%0,%1,%2,%3}, {%4,%5,%6,%7}, {%8,%9}, {%0,%1,%2,%3};"
                 : "+f"(d[0]), "+f"(d[1]), "+f"(d[2]), "+f"(d[3])
                 : "r"(a[0]), "r"(a[1]), "r"(a[2]), "r"(a[3]), "r"(b0), "r"(b1));
}

// ---------------- K0: zero histogram ----------------
__global__ void k_zero() {
    int i = blockIdx.x * blockDim.x + threadIdx.x;
    if (i < NN) g_cnt[i] = 0;
}

// ---------------- K0b: pre-round W to tf32 (stored as fp32 bits, low 13 bits zero) --
__global__ void k_wt(const float* __restrict__ W) {
    int i = blockIdx.x * blockDim.x + threadIdx.x;
    if (i < FIN * FOUT) g_wh[i] = __uint_as_float(tf32r(W[i]));
}

// ---------------- K1: single-product tf32 mma.sync GEMM, 128x128, 2 CTAs/SM --------
// h ~= tf32(a) * tf32(b); error ~2.8e-4 (A) + 2.8e-4 (B), RSS with fp16 msgs ~4.5e-4.
__global__ __launch_bounds__(256, 2) void k_gemm(const float* __restrict__ X,
                                                 const float* __restrict__ att_src,
                                                 const float* __restrict__ att_dst) {
    __shared__ __align__(16) float As[2][128][PAK];   // [buf][m][k]
    __shared__ __align__(16) float Bs[2][KC][PBN];    // [buf][k][n] (pre-rounded tf32)
    __shared__ float s_as[128], s_ad[128];

    const int tid  = threadIdx.x;
    const int wid  = tid >> 5;
    const int lane = tid & 31;
    const int f0   = blockIdx.x * 128;
    const int m0   = blockIdx.y * 128;

    if (tid < 128) {
        s_as[tid] = att_src[f0 + tid];
        s_ad[tid] = att_dst[f0 + tid];
    }

    const int warp_m = wid & 3;           // 0..3 -> 32-row slice
    const int warp_n = wid >> 2;          // 0..1 -> 64-col slice (2 heads)
    const int mb = warp_m * 32;
    const int nb = warp_n * 64;
    const int lr = lane >> 2;             // 0..7
    const int lc = lane & 3;              // 0..3

    const int rA = tid >> 2;
    const int qA = tid & 3;
    const int kB = tid >> 5;
    const int nqB = tid & 31;

    float acc[2][8][4];
    #pragma unroll
    for (int i = 0; i < 2; i++)
        #pragma unroll
        for (int j = 0; j < 8; j++)
            #pragma unroll
            for (int q = 0; q < 4; q++) acc[i][j][q] = 0.0f;

    auto load_chunk = [&](int kt, int buf) {
        #pragma unroll
        for (int j = 0; j < 2; j++) {
            int r = rA + 64 * j;
            int valid = (m0 + r) < NN ? 16 : 0;
            cpa16(smem_u32(&As[buf][r][qA * 4]),
                  X + (size_t)(m0 + r) * FIN + kt * KC + qA * 4, valid);
        }
        #pragma unroll
        for (int j = 0; j < 2; j++) {
            int k = kB + 8 * j;
            cpa16(smem_u32(&Bs[buf][k][nqB * 4]),
                  g_wh + (size_t)(kt * KC + k) * FOUT + f0 + nqB * 4, 16);
        }
    };

    load_chunk(0, 0);
    asm volatile("cp.async.commit_group;" ::: "memory");

    int buf = 0;
    for (int kt = 0; kt < NCH; kt++) {
        if (kt + 1 < NCH) {
            load_chunk(kt + 1, buf ^ 1);
            asm volatile("cp.async.commit_group;" ::: "memory");
            asm volatile("cp.async.wait_group 1;" ::: "memory");
        } else {
            asm volatile("cp.async.wait_group 0;" ::: "memory");
        }
        __syncthreads();

        #pragma unroll
        for (int k8 = 0; k8 < KC / 8; k8++) {
            const int kb = k8 * 8;
            uint32_t ahi[2][4];
            #pragma unroll
            for (int wm = 0; wm < 2; wm++) {
                int r = mb + wm * 16 + lr;
                ahi[wm][0] = tf32r(As[buf][r][kb + lc]);
                ahi[wm][1] = tf32r(As[buf][r + 8][kb + lc]);
                ahi[wm][2] = tf32r(As[buf][r][kb + lc + 4]);
                ahi[wm][3] = tf32r(As[buf][r + 8][kb + lc + 4]);
            }
            #pragma unroll
            for (int wn = 0; wn < 8; wn++) {
                int bc = nb + wn * 8 + lr;
                uint32_t bh0 = __float_as_uint(Bs[buf][kb + lc][bc]);      // pre-rounded
                uint32_t bh1 = __float_as_uint(Bs[buf][kb + lc + 4][bc]);
                #pragma unroll
                for (int wm = 0; wm < 2; wm++)
                    mma8(acc[wm][wn], ahi[wm], bh0, bh1);
            }
        }
        __syncthreads();
        buf ^= 1;
    }

    // ---- epilogue: h store (fp16) + fused a_src/a_dst ----
    // acc frag: d0=(lr, 2lc), d1=(lr, 2lc+1), d2=(lr+8, 2lc), d3=(lr+8, 2lc+1)
    #pragma unroll
    for (int wm = 0; wm < 2; wm++) {
        #pragma unroll
        for (int half = 0; half < 2; half++) {
            int m = m0 + mb + wm * 16 + half * 8 + lr;
            bool mval = m < NN;
            if (mval) {
                __half* hp = g_hh + (size_t)m * FOUT + f0 + nb + lc * 2;
                #pragma unroll
                for (int wn = 0; wn < 8; wn++) {
                    __half2 hv = __floats2half2_rn(acc[wm][wn][2 * half],
                                                   acc[wm][wn][2 * half + 1]);
                    *(__half2*)(hp + wn * 8) = hv;
                }
            }
            float psA = 0.f, pdA = 0.f, psB = 0.f, pdB = 0.f;
            #pragma unroll
            for (int wn = 0; wn < 8; wn++) {
                int col = nb + wn * 8 + lc * 2;
                float v0 = acc[wm][wn][2 * half];
                float v1 = acc[wm][wn][2 * half + 1];
                float s = v0 * s_as[col] + v1 * s_as[col + 1];
                float d = v0 * s_ad[col] + v1 * s_ad[col + 1];
                if (wn < 4) { psA += s; pdA += d; }
                else        { psB += s; pdB += d; }
            }
            #pragma unroll
            for (int off = 1; off < 4; off <<= 1) {
                psA += __shfl_xor_sync(0xffffffffu, psA, off);
                pdA += __shfl_xor_sync(0xffffffffu, pdA, off);
                psB += __shfl_xor_sync(0xffffffffu, psB, off);
                pdB += __shfl_xor_sync(0xffffffffu, pdB, off);
            }
            if (lc == 0 && mval) {
                int headA = ((f0 + nb) >> 5);
                g_asrc[m * HEADS + headA]     = psA;
                g_adst[m * HEADS + headA]     = pdA;
                g_asrc[m * HEADS + headA + 1] = psB;
                g_adst[m * HEADS + headA + 1] = pdB;
            }
        }
    }
}

// ---------------- K2: degree histogram ----------------
__global__ __launch_bounds__(256) void k_hist(const int* __restrict__ ei) {
    int e = blockIdx.x * blockDim.x + threadIdx.x;
    if (e < NE) atomicAdd(&g_cnt[ei[NE + e]], 1);
}

// ---------------- K3a/b/c: multi-block scan ----------------
__global__ __launch_bounds__(256) void k_scan1() {
    __shared__ int sp[256];
    int b = blockIdx.x, t = threadIdx.x;
    int idx = b * 256 + t;
    int v = (idx < NN) ? g_cnt[idx] : 0;
    sp[t] = v;
    __syncthreads();
    #pragma unroll
    for (int off = 1; off < 256; off <<= 1) {
        int u = (t >= off) ? sp[t - off] : 0;
        __syncthreads();
        sp[t] += u;
        __syncthreads();
    }
    if (idx < NN) g_off[idx] = sp[t] - v;
    if (t == 255) g_blk[b] = sp[255];
}
__global__ __launch_bounds__(256) void k_scan2() {
    __shared__ int sp[256];
    int t = threadIdx.x;
    int v = (t < NBLK) ? g_blk[t] : 0;
    sp[t] = v;
    __syncthreads();
    #pragma unroll
    for (int off = 1; off < 256; off <<= 1) {
        int u = (t >= off) ? sp[t - off] : 0;
        __syncthreads();
        sp[t] += u;
        __syncthreads();
    }
    if (t < NBLK) g_blkoff[t] = sp[t] - v;
}
__global__ __launch_bounds__(256) void k_scan3() {
    int idx = blockIdx.x * blockDim.x + threadIdx.x;
    if (idx < NN) {
        int o = g_off[idx] + g_blkoff[idx >> 8];
        g_off[idx] = o;
        g_cur[idx] = o;
    }
    if (idx == 0) g_off[NN] = NE;
}

// ---------------- K4: scatter ----------------
__global__ __launch_bounds__(256) void k_scatter(const int* __restrict__ ei) {
    int e = blockIdx.x * blockDim.x + threadIdx.x;
    if (e >= NE) return;
    int src = ei[e];
    int dst = ei[NE + e];
    int p = atomicAdd(&g_cur[dst], 1);
    g_sorted[p] = src;
}

// ---------------- K5: single-pass softmax-weighted aggregation (warp per node) -----
// out = (sum_e exp(v_e) * h_e) / (sum_e exp(v_e))  -> normalize once at the end.
__global__ __launch_bounds__(256) void k_node(const float* __restrict__ bias,
                                              float* __restrict__ out) {
    int n = (blockIdx.x * blockDim.x + threadIdx.x) >> 5;
    if (n >= NN) return;
    int lane = threadIdx.x & 31;

    int s0 = g_off[n];
    int s1 = g_off[n + 1];

    float ad = g_adst[n * HEADS + (lane & 7)];   // lane (lane&7) owns head lane&7

    float den = 0.0f;
    float acc[8];
    #pragma unroll
    for (int j = 0; j < 8; j++) acc[j] = 0.0f;

    for (int e = s0; e < s1; e++) {
        int s = g_sorted[e];
        float v = g_asrc[s * HEADS + (lane & 7)] + ad;
        v = (v > 0.0f) ? v : NEG_SLOPE * v;
        float w = __expf(v);
        den += w;
        float a = __shfl_sync(0xffffffffu, w, lane >> 2);    // head for my 8 cols
        uint4 hv = *(const uint4*)(g_hh + (size_t)s * FOUT + lane * 8);
        const __half2* hp = (const __half2*)&hv;
        #pragma unroll
        for (int j = 0; j < 4; j++) {
            float2 f = __half22float2(hp[j]);
            acc[2 * j]     += a * f.x;
            acc[2 * j + 1] += a * f.y;
        }
    }

    float dhead = __shfl_sync(0xffffffffu, den, lane >> 2);
    float rden = (dhead > 0.0f) ? (1.0f / dhead) : 0.0f;

    const float* bp = bias + lane * 8;
    float* op = out + (size_t)n * FOUT + lane * 8;
    float4 o0 = make_float4(acc[0] * rden + bp[0], acc[1] * rden + bp[1],
                            acc[2] * rden + bp[2], acc[3] * rden + bp[3]);
    float4 o1 = make_float4(acc[4] * rden + bp[4], acc[5] * rden + bp[5],
                            acc[6] * rden + bp[6], acc[7] * rden + bp[7]);
    *(float4*)(op)     = o0;
    *(float4*)(op + 4) = o1;
}

// ---------------- launch ----------------
extern "C" void kernel_launch(void* const* d_in, const int* in_sizes, int n_in,
                              void* d_out, int out_size) {
    const float* x       = (const float*)d_in[0];
    const float* W       = (const float*)d_in[1];
    const float* att_src = (const float*)d_in[2];
    const float* att_dst = (const float*)d_in[3];
    const float* bias    = (const float*)d_in[4];
    const int*   ei      = (const int*)d_in[5];
    float*       out     = (float*)d_out;

    int eb = (NE + 255) / 256;

    k_zero<<<(NN + 255) / 256, 256>>>();                 // 1
    k_hist<<<eb, 256>>>(ei);                             // 2
    k_wt<<<(FIN * FOUT + 255) / 256, 256>>>(W);          // 3

    dim3 ggrid(FOUT / 128, (NN + 127) / 128);            // (2, 391)
    k_gemm<<<ggrid, 256>>>(x, att_src, att_dst);         // 4  <- profiled slot

    k_scan1<<<NBLK, 256>>>();                            // 5
    k_scan2<<<1, 256>>>();                               // 6
    k_scan3<<<NBLK, 256>>>();                            // 7
    k_scatter<<<eb, 256>>>(ei);                          // 8
    k_node<<<(NN * 32 + 255) / 256, 256>>>(bias, out);   // 9
}

// round 17
// speedup vs baseline: 1.5465x; 1.0710x over previous
#include <cuda_runtime.h>
#include <cuda_fp16.h>
#include <cstdint>

// GATSingleLayer: N=50000, E=1e6, F_IN=256, HEADS=8, F_HEAD=32
#define NN      50000
#define NE      1000000
#define FIN     256
#define HEADS   8
#define FHEAD   32
#define FOUT    256
#define NEG_SLOPE 0.2f
#define NBLK    196              // ceil(NN/256)
#define KC      32               // K chunk (doubled: fewer barriers)
#define NCH     (FIN / KC)       // 8 chunks
#define PAK     36               // A pitch: bank (4r+c)%32 distinct over fragment lanes
#define PBN     136              // B pitch: bank (8lc+lr)%32 distinct (fixes 132's 2-way)
// dynamic smem (floats): A[2][128][PAK] then B[2][KC][PBN]
#define APL     (128 * PAK)                  // 4608
#define BPL     (KC * PBN)                   // 4352
#define AOF(b)  ((b) * APL)
#define BOF(b)  (2 * APL + (b) * BPL)
#define SMEM_BYTES ((2 * APL + 2 * BPL) * 4) // 71680

// ---------------- device scratch ----------------
__device__ __align__(16) __half g_hh[(size_t)NN * FOUT]; // 25.6 MB fp16 messages
__device__ __align__(16) float g_asrc[NN * HEADS];
__device__ __align__(16) float g_adst[NN * HEADS];
__device__ __align__(16) float g_wh[FIN * FOUT];         // tf32-rounded W (fp32 bits)
__device__ int g_cnt[NN];        // zero-init at load; k_scan3 re-zeros for next run
__device__ int g_off[NN + 1];
__device__ int g_cur[NN];
__device__ int g_sorted[NE];
__device__ int g_blk[NBLK];
__device__ int g_blkoff[NBLK];

// ---------------- helpers ----------------
__device__ __forceinline__ uint32_t smem_u32(const void* p) {
    uint32_t a;
    asm("{ .reg .u64 t; cvta.to.shared.u64 t, %1; cvt.u32.u64 %0, t; }" : "=r"(a) : "l"(p));
    return a;
}
__device__ __forceinline__ void cpa16(uint32_t dst, const void* src, int szvalid) {
    asm volatile("cp.async.cg.shared.global [%0], [%1], 16, %2;"
                 :: "r"(dst), "l"(src), "r"(szvalid) : "memory");
}
__device__ __forceinline__ uint32_t tf32r(float x) {
    uint32_t u;
    asm("cvt.rna.tf32.f32 %0, %1;" : "=r"(u) : "f"(x));
    return u;
}
__device__ __forceinline__ void mma8(float* d, const uint32_t* a, uint32_t b0, uint32_t b1) {
    asm volatile("mma.sync.aligned.m16n8k8.row.col.f32.tf32.tf32.f32 "
                 "{%0,%1,%2,%3}, {%4,%5,%6,%7}, {%8,%9}, {%0,%1,%2,%3};"
                 : "+f"(d[0]), "+f"(d[1]), "+f"(d[2]), "+f"(d[3])
                 : "r"(a[0]), "r"(a[1]), "r"(a[2]), "r"(a[3]), "r"(b0), "r"(b1));
}

// ---------------- K0b: pre-round W to tf32 (fp32 bits, low 13 bits zero) -----------
__global__ void k_wt(const float* __restrict__ W) {
    int i = blockIdx.x * blockDim.x + threadIdx.x;
    if (i < FIN * FOUT) g_wh[i] = __uint_as_float(tf32r(W[i]));
}

// ---------------- K1: single-product tf32 mma.sync GEMM, KC=32, 2 CTAs/SM ----------
__global__ __launch_bounds__(256, 2) void k_gemm(const float* __restrict__ X,
                                                 const float* __restrict__ att_src,
                                                 const float* __restrict__ att_dst) {
    extern __shared__ __align__(16) float smf[];
    __shared__ float s_as[128], s_ad[128];

    const int tid  = threadIdx.x;
    const int wid  = tid >> 5;
    const int lane = tid & 31;
    const int f0   = blockIdx.x * 128;
    const int m0   = blockIdx.y * 128;

    if (tid < 128) {
        s_as[tid] = att_src[f0 + tid];
        s_ad[tid] = att_dst[f0 + tid];
    }

    const int warp_m = wid & 3;           // 0..3 -> 32-row slice
    const int warp_n = wid >> 2;          // 0..1 -> 64-col slice (2 heads)
    const int mb = warp_m * 32;
    const int nb = warp_n * 64;
    const int lr = lane >> 2;             // 0..7
    const int lc = lane & 3;              // 0..3

    // loaders: KC=32 chunk = 16 KB per operand = 4 x 16B per thread
    const int rA  = tid >> 3;             // 0..31 (+32j)
    const int sA  = tid & 7;              // 16B segment within 128B row
    const int kB  = tid >> 5;             // 0..7 (+8j)
    const int nqB = tid & 31;

    float acc[2][8][4];
    #pragma unroll
    for (int i = 0; i < 2; i++)
        #pragma unroll
        for (int j = 0; j < 8; j++)
            #pragma unroll
            for (int q = 0; q < 4; q++) acc[i][j][q] = 0.0f;

    auto load_chunk = [&](int kt, int buf) {
        #pragma unroll
        for (int j = 0; j < 4; j++) {
            int r = rA + 32 * j;
            int valid = (m0 + r) < NN ? 16 : 0;
            cpa16(smem_u32(&smf[AOF(buf) + r * PAK + sA * 4]),
                  X + (size_t)(m0 + r) * FIN + kt * KC + sA * 4, valid);
        }
        #pragma unroll
        for (int j = 0; j < 4; j++) {
            int k = kB + 8 * j;
            cpa16(smem_u32(&smf[BOF(buf) + k * PBN + nqB * 4]),
                  g_wh + (size_t)(kt * KC + k) * FOUT + f0 + nqB * 4, 16);
        }
    };

    load_chunk(0, 0);
    asm volatile("cp.async.commit_group;" ::: "memory");

    int buf = 0;
    for (int kt = 0; kt < NCH; kt++) {
        if (kt + 1 < NCH) {
            load_chunk(kt + 1, buf ^ 1);
            asm volatile("cp.async.commit_group;" ::: "memory");
            asm volatile("cp.async.wait_group 1;" ::: "memory");
        } else {
            asm volatile("cp.async.wait_group 0;" ::: "memory");
        }
        __syncthreads();

        #pragma unroll
        for (int k8 = 0; k8 < KC / 8; k8++) {
            const int kb = k8 * 8;
            const int ao = AOF(buf), bo = BOF(buf);
            uint32_t ahi[2][4];
            #pragma unroll
            for (int wm = 0; wm < 2; wm++) {
                int r = mb + wm * 16 + lr;
                ahi[wm][0] = tf32r(smf[ao + r * PAK + kb + lc]);
                ahi[wm][1] = tf32r(smf[ao + (r + 8) * PAK + kb + lc]);
                ahi[wm][2] = tf32r(smf[ao + r * PAK + kb + lc + 4]);
                ahi[wm][3] = tf32r(smf[ao + (r + 8) * PAK + kb + lc + 4]);
            }
            #pragma unroll
            for (int wn = 0; wn < 8; wn++) {
                int bc = nb + wn * 8 + lr;
                uint32_t bh0 = __float_as_uint(smf[bo + (kb + lc) * PBN + bc]);
                uint32_t bh1 = __float_as_uint(smf[bo + (kb + lc + 4) * PBN + bc]);
                #pragma unroll
                for (int wm = 0; wm < 2; wm++)
                    mma8(acc[wm][wn], ahi[wm], bh0, bh1);
            }
        }
        __syncthreads();
        buf ^= 1;
    }

    // ---- epilogue: h store (fp16) + fused a_src/a_dst ----
    // acc frag: d0=(lr, 2lc), d1=(lr, 2lc+1), d2=(lr+8, 2lc), d3=(lr+8, 2lc+1)
    #pragma unroll
    for (int wm = 0; wm < 2; wm++) {
        #pragma unroll
        for (int half = 0; half < 2; half++) {
            int m = m0 + mb + wm * 16 + half * 8 + lr;
            bool mval = m < NN;
            if (mval) {
                __half* hp = g_hh + (size_t)m * FOUT + f0 + nb + lc * 2;
                #pragma unroll
                for (int wn = 0; wn < 8; wn++) {
                    __half2 hv = __floats2half2_rn(acc[wm][wn][2 * half],
                                                   acc[wm][wn][2 * half + 1]);
                    *(__half2*)(hp + wn * 8) = hv;
                }
            }
            float psA = 0.f, pdA = 0.f, psB = 0.f, pdB = 0.f;
            #pragma unroll
            for (int wn = 0; wn < 8; wn++) {
                int col = nb + wn * 8 + lc * 2;
                float v0 = acc[wm][wn][2 * half];
                float v1 = acc[wm][wn][2 * half + 1];
                float s = v0 * s_as[col] + v1 * s_as[col + 1];
                float d = v0 * s_ad[col] + v1 * s_ad[col + 1];
                if (wn < 4) { psA += s; pdA += d; }
                else        { psB += s; pdB += d; }
            }
            #pragma unroll
            for (int off = 1; off < 4; off <<= 1) {
                psA += __shfl_xor_sync(0xffffffffu, psA, off);
                pdA += __shfl_xor_sync(0xffffffffu, pdA, off);
                psB += __shfl_xor_sync(0xffffffffu, psB, off);
                pdB += __shfl_xor_sync(0xffffffffu, pdB, off);
            }
            if (lc == 0 && mval) {
                int headA = ((f0 + nb) >> 5);
                g_asrc[m * HEADS + headA]     = psA;
                g_adst[m * HEADS + headA]     = pdA;
                g_asrc[m * HEADS + headA + 1] = psB;
                g_adst[m * HEADS + headA + 1] = pdB;
            }
        }
    }
}

// ---------------- K2: degree histogram (int4 edge reads) ----------------
__global__ __launch_bounds__(256) void k_hist(const int* __restrict__ ei) {
    int i = blockIdx.x * blockDim.x + threadIdx.x;
    if (i >= NE / 4) return;
    int4 d = ((const int4*)(ei + NE))[i];
    atomicAdd(&g_cnt[d.x], 1);
    atomicAdd(&g_cnt[d.y], 1);
    atomicAdd(&g_cnt[d.z], 1);
    atomicAdd(&g_cnt[d.w], 1);
}

// ---------------- K3a/b/c: multi-block scan ----------------
__global__ __launch_bounds__(256) void k_scan1() {
    __shared__ int sp[256];
    int b = blockIdx.x, t = threadIdx.x;
    int idx = b * 256 + t;
    int v = (idx < NN) ? g_cnt[idx] : 0;
    sp[t] = v;
    __syncthreads();
    #pragma unroll
    for (int off = 1; off < 256; off <<= 1) {
        int u = (t >= off) ? sp[t - off] : 0;
        __syncthreads();
        sp[t] += u;
        __syncthreads();
    }
    if (idx < NN) g_off[idx] = sp[t] - v;
    if (t == 255) g_blk[b] = sp[255];
}
__global__ __launch_bounds__(256) void k_scan2() {
    __shared__ int sp[256];
    int t = threadIdx.x;
    int v = (t < NBLK) ? g_blk[t] : 0;
    sp[t] = v;
    __syncthreads();
    #pragma unroll
    for (int off = 1; off < 256; off <<= 1) {
        int u = (t >= off) ? sp[t - off] : 0;
        __syncthreads();
        sp[t] += u;
        __syncthreads();
    }
    if (t < NBLK) g_blkoff[t] = sp[t] - v;
}
__global__ __launch_bounds__(256) void k_scan3() {
    int idx = blockIdx.x * blockDim.x + threadIdx.x;
    if (idx < NN) {
        int o = g_off[idx] + g_blkoff[idx >> 8];
        g_off[idx] = o;
        g_cur[idx] = o;
        g_cnt[idx] = 0;          // re-zero for the next kernel_launch call
    }
    if (idx == 0) g_off[NN] = NE;
}

// ---------------- K4: scatter (int4 edge reads) ----------------
__global__ __launch_bounds__(256) void k_scatter(const int* __restrict__ ei) {
    int i = blockIdx.x * blockDim.x + threadIdx.x;
    if (i >= NE / 4) return;
    int4 s4 = ((const int4*)ei)[i];
    int4 d4 = ((const int4*)(ei + NE))[i];
    g_sorted[atomicAdd(&g_cur[d4.x], 1)] = s4.x;
    g_sorted[atomicAdd(&g_cur[d4.y], 1)] = s4.y;
    g_sorted[atomicAdd(&g_cur[d4.z], 1)] = s4.z;
    g_sorted[atomicAdd(&g_cur[d4.w], 1)] = s4.w;
}

// ---------------- K5: single-pass softmax-weighted aggregation (warp per node) -----
__global__ __launch_bounds__(256) void k_node(const float* __restrict__ bias,
                                              float* __restrict__ out) {
    int n = (blockIdx.x * blockDim.x + threadIdx.x) >> 5;
    if (n >= NN) return;
    int lane = threadIdx.x & 31;

    int s0 = g_off[n];
    int s1 = g_off[n + 1];

    float ad = g_adst[n * HEADS + (lane & 7)];

    float den = 0.0f;
    float acc[8];
    #pragma unroll
    for (int j = 0; j < 8; j++) acc[j] = 0.0f;

    for (int e = s0; e < s1; e++) {
        int s = g_sorted[e];
        float v = g_asrc[s * HEADS + (lane & 7)] + ad;
        v = (v > 0.0f) ? v : NEG_SLOPE * v;
        float w = __expf(v);
        den += w;
        float a = __shfl_sync(0xffffffffu, w, lane >> 2);    // head for my 8 cols
        uint4 hv = *(const uint4*)(g_hh + (size_t)s * FOUT + lane * 8);
        const __half2* hp = (const __half2*)&hv;
        #pragma unroll
        for (int j = 0; j < 4; j++) {
            float2 f = __half22float2(hp[j]);
            acc[2 * j]     += a * f.x;
            acc[2 * j + 1] += a * f.y;
        }
    }

    float dhead = __shfl_sync(0xffffffffu, den, lane >> 2);
    float rden = (dhead > 0.0f) ? (1.0f / dhead) : 0.0f;

    const float* bp = bias + lane * 8;
    float* op = out + (size_t)n * FOUT + lane * 8;
    float4 o0 = make_float4(acc[0] * rden + bp[0], acc[1] * rden + bp[1],
                            acc[2] * rden + bp[2], acc[3] * rden + bp[3]);
    float4 o1 = make_float4(acc[4] * rden + bp[4], acc[5] * rden + bp[5],
                            acc[6] * rden + bp[6], acc[7] * rden + bp[7]);
    *(float4*)(op)     = o0;
    *(float4*)(op + 4) = o1;
}

// ---------------- launch ----------------
extern "C" void kernel_launch(void* const* d_in, const int* in_sizes, int n_in,
                              void* d_out, int out_size) {
    const float* x       = (const float*)d_in[0];
    const float* W       = (const float*)d_in[1];
    const float* att_src = (const float*)d_in[2];
    const float* att_dst = (const float*)d_in[3];
    const float* bias    = (const float*)d_in[4];
    const int*   ei      = (const int*)d_in[5];
    float*       out     = (float*)d_out;

    cudaFuncSetAttribute(k_gemm, cudaFuncAttributeMaxDynamicSharedMemorySize, SMEM_BYTES);

    int e4 = (NE / 4 + 255) / 256;

    k_hist<<<e4, 256>>>(ei);                             // 1
    k_wt<<<(FIN * FOUT + 255) / 256, 256>>>(W);          // 2
    k_scan1<<<NBLK, 256>>>();                            // 3

    dim3 ggrid(FOUT / 128, (NN + 127) / 128);            // (2, 391)
    k_gemm<<<ggrid, 256, SMEM_BYTES>>>(x, att_src, att_dst);  // 4 <- profiled slot

    k_scan2<<<1, 256>>>();                               // 5
    k_scan3<<<NBLK, 256>>>();                            // 6
    k_scatter<<<e4, 256>>>(ei);                          // 7
    k_node<<<(NN * 32 + 255) / 256, 256>>>(bias, out);   // 8
}